// round 11
// baseline (speedup 1.0000x reference)
#include <cuda_runtime.h>
#include <cuda_fp16.h>
#include <math.h>
#include <cstdint>

#define B_ 2
#define T_ 2048
#define E_ 2048
#define H_ 16
#define D_ 128
#define M_ (B_*T_)             // 4096
#define QKV_N (B_*H_*T_*D_)    // 8388608
#define WN_ (E_*E_)            // 4194304
#define QSCALE 0.08838834764831845f   // 1/sqrt(128)

// ---------------- scratch ----------------------------------------------------
__device__ float  g_Q[QKV_N];          // fp32 Q (pre-rope), head-major [b,h,t,d]
__device__ float  g_K[QKV_N];
__device__ __half g_Qh[QKV_N];         // post-rope, scaled, f16
__device__ __half g_Kh[QKV_N];         // post-rope, f16
__device__ __half g_Vh[QKV_N];
__device__ __half g_Yh[QKV_N];         // attn out [b,t,h*128+d]
__device__ __half g_Xh[M_*E_];
__device__ __half g_Wh[4*WN_];         // Wq,Wk,Wv,Wo f16
__device__ float  g_theta[64];

// ---------------- helpers ----------------------------------------------------
__device__ __forceinline__ uint32_t smem_u32(const void* p) {
    uint32_t a;
    asm("{ .reg .u64 t; cvta.to.shared.u64 t, %1; cvt.u32.u64 %0, t; }" : "=r"(a) : "l"(p));
    return a;
}
__device__ __forceinline__ void cp16(uint32_t d, const void* g) {
    asm volatile("cp.async.cg.shared.global [%0], [%1], 16;" :: "r"(d), "l"(g));
}
__device__ __forceinline__ void ldsm4(uint32_t (&r)[4], uint32_t addr) {
    asm volatile("ldmatrix.sync.aligned.m8n8.x4.shared.b16 {%0,%1,%2,%3}, [%4];"
        : "=r"(r[0]), "=r"(r[1]), "=r"(r[2]), "=r"(r[3]) : "r"(addr));
}
__device__ __forceinline__ void ldsm4t(uint32_t (&r)[4], uint32_t addr) {
    asm volatile("ldmatrix.sync.aligned.m8n8.x4.trans.shared.b16 {%0,%1,%2,%3}, [%4];"
        : "=r"(r[0]), "=r"(r[1]), "=r"(r[2]), "=r"(r[3]) : "r"(addr));
}
__device__ __forceinline__ void mma16816(float (&d)[4], const uint32_t (&a)[4],
                                         uint32_t b0, uint32_t b1) {
    asm volatile("mma.sync.aligned.m16n8k16.row.col.f32.f16.f16.f32 "
        "{%0,%1,%2,%3},{%4,%5,%6,%7},{%8,%9},{%0,%1,%2,%3};"
        : "+f"(d[0]), "+f"(d[1]), "+f"(d[2]), "+f"(d[3])
        : "r"(a[0]), "r"(a[1]), "r"(a[2]), "r"(a[3]), "r"(b0), "r"(b1));
}
__device__ __forceinline__ uint32_t pack2(float x0, float x1) {
    __half2 h = __floats2half2_rn(x0, x1);
    return *(uint32_t*)&h;
}
__device__ __forceinline__ float qmax(float v) {
    v = fmaxf(v, __shfl_xor_sync(0xffffffffu, v, 1));
    v = fmaxf(v, __shfl_xor_sync(0xffffffffu, v, 2));
    return v;
}
__device__ __forceinline__ float qsum(float v) {
    v += __shfl_xor_sync(0xffffffffu, v, 1);
    v += __shfl_xor_sync(0xffffffffu, v, 2);
    return v;
}

// ---------------------------------------------------------------------------
__global__ void theta_init_kernel() {
    int j = threadIdx.x;
    if (j < 64) g_theta[j] = (float)pow(10000.0, -(double)j / 64.0);
}

// x f32 -> f16
__global__ void f2h_kernel(const float* __restrict__ src, __half* __restrict__ dst, int n4) {
    int i = blockIdx.x * blockDim.x + threadIdx.x;
    if (i < n4) {
        float4 v = ((const float4*)src)[i];
        uint32_t* d = (uint32_t*)dst + (size_t)i * 2;
        d[0] = pack2(v.x, v.y);
        d[1] = pack2(v.z, v.w);
    }
}

// all 4 weights f32 -> f16, one launch. grid.y selects matrix.
__global__ void w_f2h_kernel(const float* __restrict__ w0, const float* __restrict__ w1,
                             const float* __restrict__ w2, const float* __restrict__ w3) {
    int i = blockIdx.x * blockDim.x + threadIdx.x;
    if (i >= WN_/4) return;
    const float* srcs[4] = { w0, w1, w2, w3 };
    const float* src = srcs[blockIdx.y];
    float4 v = ((const float4*)src)[i];
    uint32_t* d = (uint32_t*)(g_Wh + (size_t)blockIdx.y * WN_) + (size_t)i * 2;
    d[0] = pack2(v.x, v.y);
    d[1] = pack2(v.z, v.w);
}

// ---------------------------------------------------------------------------
// GEMM core: C tile [128x128] = A[M,K]@W[N,K]^T + bias, f16 HMMA.
// 128 threads (4 warps, 2x2), warp tile 64x64, BK=32, 4-stage cp.async.
// HMMA:LDSM = 32:8 per k16 — compute-dominant inner loop.
// mode 0: ->g_Q fp32 head-major   mode 1: ->g_K fp32 head-major
// mode 2: ->g_Vh f16 head-major   mode 3: ->outF fp32 row-major
// ---------------------------------------------------------------------------
#define GBK 32
#define GPITCH 80               // bytes per smem row (64 data + 16 pad)
#define GMAT_B (128*GPITCH)     // 10240 B per matrix per stage
#define GSTAGE_B (2*GMAT_B)     // 20480
#define GEMM_SMEM (4*GSTAGE_B)  // 81920

__device__ __forceinline__ void gemm_load_stage(
    uint32_t sb, const __half* Ah, const __half* Bh,
    int m0, int n0, int k0, int tid)
{
    #pragma unroll
    for (int p = 0; p < 8; ++p) {
        int idx = tid + p * 128;          // 0..1023
        int mat = idx >> 9;               // 0: A, 1: B
        int r = (idx >> 2) & 127;
        int c16 = idx & 3;
        const __half* src = (mat ? Bh : Ah)
                          + (size_t)((mat ? n0 : m0) + r) * E_ + k0 + c16 * 8;
        cp16(sb + mat * GMAT_B + r * GPITCH + c16 * 16, src);
    }
    asm volatile("cp.async.commit_group;" ::: "memory");
}

__device__ __forceinline__ void gemm_core(
    const __half* __restrict__ Ah, const __half* __restrict__ Bh,
    const float* __restrict__ bias, float* __restrict__ outF,
    int mode, uint32_t sbase)
{
    const int tid = threadIdx.x;
    const int lane = tid & 31;
    const int w = tid >> 5;
    const int wm = w >> 1, wn = w & 1;
    const int n0 = blockIdx.x * 128;
    const int m0 = blockIdx.y * 128;

    float acc[4][8][4] = {};

    // prologue: chunks 0..2 -> slots 0..2
    gemm_load_stage(sbase,              Ah, Bh, m0, n0, 0,      tid);
    gemm_load_stage(sbase + GSTAGE_B,   Ah, Bh, m0, n0, GBK,    tid);
    gemm_load_stage(sbase + 2*GSTAGE_B, Ah, Bh, m0, n0, 2*GBK,  tid);

    const int NCH = E_ / GBK;   // 64
    for (int i = 0; i < NCH; ++i) {
        asm volatile("cp.async.wait_group 2;" ::: "memory");   // chunk i landed
        __syncthreads();   // slot (i+3)%4 == (i-1)%4 no longer read

        if (i + 3 < NCH)
            gemm_load_stage(sbase + ((i + 3) & 3) * GSTAGE_B,
                            Ah, Bh, m0, n0, (i + 3) * GBK, tid);
        else
            asm volatile("cp.async.commit_group;" ::: "memory");  // uniform count

        const uint32_t sb = sbase + (i & 3) * GSTAGE_B;
        #pragma unroll
        for (int kk = 0; kk < 2; ++kk) {
            uint32_t a[4][4];
            #pragma unroll
            for (int mf = 0; mf < 4; ++mf)
                ldsm4(a[mf], sb + (wm*64 + mf*16 + (lane & 15)) * GPITCH
                           + kk*32 + (lane >> 4) * 16);
            uint32_t b[4][4];
            #pragma unroll
            for (int gg = 0; gg < 4; ++gg)
                ldsm4(b[gg], sb + GMAT_B
                           + (wn*64 + gg*16 + (lane & 7) + ((lane >> 4) & 1) * 8) * GPITCH
                           + kk*32 + ((lane >> 3) & 1) * 16);
            #pragma unroll
            for (int mf = 0; mf < 4; ++mf)
                #pragma unroll
                for (int nf = 0; nf < 8; ++nf) {
                    int g = nf >> 1, h = (nf & 1) * 2;
                    mma16816(acc[mf][nf], a[mf], b[g][h], b[g][h+1]);
                }
        }
    }

    // epilogue
    #pragma unroll
    for (int nf = 0; nf < 8; ++nf) {
        int d = wn*64 + nf*8 + (lane & 3) * 2;          // 0..127 within tile
        int gcol = n0 + d;
        float b0 = bias[gcol], b1 = bias[gcol + 1];
        #pragma unroll
        for (int mf = 0; mf < 4; ++mf) {
            int row0 = m0 + wm*64 + mf*16 + (lane >> 2);
            #pragma unroll
            for (int half = 0; half < 2; ++half) {
                int row = row0 + half * 8;
                float v0 = acc[mf][nf][half*2 + 0] + b0;
                float v1 = acc[mf][nf][half*2 + 1] + b1;
                if (mode == 3) {
                    *(float2*)(outF + (size_t)row * E_ + gcol) = make_float2(v0, v1);
                } else {
                    int b = row >> 11, t = row & (T_ - 1), h = blockIdx.x;
                    size_t idx = (((size_t)(b*H_ + h)) * T_ + t) * D_ + d;
                    if (mode == 2) {
                        *(uint32_t*)&g_Vh[idx] = pack2(v0, v1);
                    } else {
                        float* dst = (mode == 0) ? g_Q : g_K;
                        *(float2*)(dst + idx) = make_float2(v0, v1);
                    }
                }
            }
        }
    }
}

// fused Q/K/V projections: grid (16, 32, 3), z selects target
__global__ __launch_bounds__(128, 2) void qkv_gemm(
    const float* __restrict__ bq, const float* __restrict__ bk,
    const float* __restrict__ bv)
{
    extern __shared__ __align__(16) char dsmem[];
    const int mode = blockIdx.z;
    const float* bias = (mode == 0) ? bq : (mode == 1) ? bk : bv;
    gemm_core(g_Xh, g_Wh + (size_t)mode * WN_, bias, nullptr, mode, smem_u32(dsmem));
}

// output projection: grid (16, 32)
__global__ __launch_bounds__(128, 2) void out_gemm(
    const float* __restrict__ bo, float* __restrict__ outF)
{
    extern __shared__ __align__(16) char dsmem[];
    gemm_core(g_Yh, g_Wh + 3*(size_t)WN_, bo, outF, 3, smem_u32(dsmem));
}

// ---------------------------------------------------------------------------
// RoPE + scale (Q only) -> f16.
// ---------------------------------------------------------------------------
__global__ void rope_kernel() {
    const int total = B_*H_*T_*(D_/2);
    int idx = blockIdx.x * blockDim.x + threadIdx.x;
    if (idx >= total) return;
    int row = idx >> 6;
    int j   = idx & 63;
    int t   = row & (T_ - 1);
    float ang = (float)(t + 1) * g_theta[j];
    float s, c;
    sincosf(ang, &s, &c);
    int isK = blockIdx.y;
    const float* src = isK ? g_K : g_Q;
    __half* dst = isK ? g_Kh : g_Qh;
    size_t base = (size_t)row * D_;
    float x0 = src[base + j];
    float x1 = src[base + j + 64];
    float r0 = x0*c - x1*s;
    float r1 = x1*c + x0*s;
    if (!isK) { r0 *= QSCALE; r1 *= QSCALE; }
    dst[base + j]      = __float2half_rn(r0);
    dst[base + j + 64] = __float2half_rn(r1);
}

// ---------------------------------------------------------------------------
// Flash attention, causal, 1-pass f16 HMMA, fp32 softmax.
// grid (16, B*H): CTA jj processes q-tiles jj and 31-jj (uniform 33 KV-blocks).
// 128 threads (4 warps). BQ=64 (16 rows/warp), BKV=64.
// cp.async overlap: V load hidden under S+softmax, next-K load hidden under PV.
// ---------------------------------------------------------------------------
#define AT_ROW 136                       // halves per smem row (128 + 8 pad)
#define AT_ROWB (AT_ROW*2)               // bytes per smem row
#define AT_TILE (64*AT_ROW)              // halves per matrix
#define ATTN_SMEM (3*AT_TILE*2)          // Q, K, V = 52224 B

__device__ __forceinline__ void attn_cp_tile(uint32_t dst, const __half* src, int tid) {
    #pragma unroll
    for (int p = 0; p < 8; ++p) {
        int idx = tid + p * 128;
        int row = idx >> 4, c8 = idx & 15;
        cp16(dst + row * AT_ROWB + c8 * 16, src + (size_t)row * D_ + c8 * 8);
    }
}

__global__ __launch_bounds__(128) void attn_tc() {
    extern __shared__ __align__(16) __half asmem[];
    __half* sQ = asmem;
    __half* sK = asmem + AT_TILE;
    __half* sV = asmem + 2*AT_TILE;
    const uint32_t uQ = smem_u32(sQ);
    const uint32_t uK = smem_u32(sK);
    const uint32_t uV = smem_u32(sV);

    const int tid = threadIdx.x;
    const int lane = tid & 31;
    const int w = tid >> 5;
    const int jj = blockIdx.x;           // 0..15
    const int bh = blockIdx.y;
    const __half* Qhp = g_Qh + (size_t)bh * T_ * D_;
    const __half* Khp = g_Kh + (size_t)bh * T_ * D_;
    const __half* Vhp = g_Vh + (size_t)bh * T_ * D_;

    for (int hh = 0; hh < 2; ++hh) {
        const int qt = hh ? (31 - jj) : jj;
        const int q0 = qt * 64;

        // prologue: Q tile + K_0 tile (one group)
        attn_cp_tile(uQ, Qhp + (size_t)q0 * D_, tid);
        attn_cp_tile(uK, Khp, tid);
        asm volatile("cp.async.commit_group;" ::: "memory");

        float of[16][4] = {};
        float m0 = -1e30f, m1 = -1e30f, l0 = 0.f, l1 = 0.f;
        const int nblocks = qt + 1;

        for (int it = 0; it < nblocks; ++it) {
            const int k0 = it * 64;
            const bool diag = (it == nblocks - 1);

            asm volatile("cp.async.wait_group 0;" ::: "memory");   // K_it (and Q) ready
            __syncthreads();                                       // sV free (prev PV done)

            // issue V_it load — hidden under S + softmax
            attn_cp_tile(uV, Vhp + (size_t)k0 * D_, tid);
            asm volatile("cp.async.commit_group;" ::: "memory");

            // ---- S = Q K^T ----
            float sf[8][4] = {};
            #pragma unroll
            for (int k16 = 0; k16 < 8; ++k16) {
                uint32_t aqh[4];
                uint32_t aaddr = (w*16 + (lane & 15)) * AT_ROWB + k16*32 + (lane >> 4) * 16;
                ldsm4(aqh, uQ + aaddr);
                #pragma unroll
                for (int g = 0; g < 4; ++g) {
                    uint32_t kbh[4];
                    uint32_t baddr = (g*16 + (lane & 7) + ((lane >> 4) & 1) * 8) * AT_ROWB
                                   + k16*32 + ((lane >> 3) & 1) * 16;
                    ldsm4(kbh, uK + baddr);
                    mma16816(sf[2*g],   aqh, kbh[0], kbh[1]);
                    mma16816(sf[2*g+1], aqh, kbh[2], kbh[3]);
                }
            }

            // ---- mask (diagonal block only) ----
            const int rg0 = q0 + w*16 + (lane >> 2);
            if (diag) {
                #pragma unroll
                for (int n = 0; n < 8; ++n) {
                    int col = k0 + n*8 + (lane & 3) * 2;
                    if (col     > rg0)     sf[n][0] = -1e30f;
                    if (col + 1 > rg0)     sf[n][1] = -1e30f;
                    if (col     > rg0 + 8) sf[n][2] = -1e30f;
                    if (col + 1 > rg0 + 8) sf[n][3] = -1e30f;
                }
            }

            // ---- online softmax ----
            float mx0 = -1e30f, mx1 = -1e30f;
            #pragma unroll
            for (int n = 0; n < 8; ++n) {
                mx0 = fmaxf(mx0, fmaxf(sf[n][0], sf[n][1]));
                mx1 = fmaxf(mx1, fmaxf(sf[n][2], sf[n][3]));
            }
            mx0 = qmax(mx0); mx1 = qmax(mx1);
            float mn0 = fmaxf(m0, mx0), mn1 = fmaxf(m1, mx1);
            float a0 = __expf(m0 - mn0), a1 = __expf(m1 - mn1);
            m0 = mn0; m1 = mn1;

            uint32_t pa[4][4];
            float s0 = 0.f, s1 = 0.f;
            #pragma unroll
            for (int n = 0; n < 8; ++n) {
                float p0 = __expf(sf[n][0] - mn0);
                float p1 = __expf(sf[n][1] - mn0);
                float p2 = __expf(sf[n][2] - mn1);
                float p3 = __expf(sf[n][3] - mn1);
                s0 += p0 + p1; s1 += p2 + p3;
                int kt = n >> 1, o = (n & 1) * 2;
                pa[kt][o + 0] = pack2(p0, p1);
                pa[kt][o + 1] = pack2(p2, p3);
            }
            s0 = qsum(s0); s1 = qsum(s1);
            l0 = l0 * a0 + s0;
            l1 = l1 * a1 + s1;
            #pragma unroll
            for (int n = 0; n < 16; ++n) {
                of[n][0] *= a0; of[n][1] *= a0;
                of[n][2] *= a1; of[n][3] *= a1;
            }

            asm volatile("cp.async.wait_group 0;" ::: "memory");   // V_it ready
            __syncthreads();                                       // sK free (all past S)

            // issue K_{it+1} load — hidden under PV
            if (it + 1 < nblocks) {
                attn_cp_tile(uK, Khp + (size_t)(k0 + 64) * D_, tid);
                asm volatile("cp.async.commit_group;" ::: "memory");
            }

            // ---- O += P V ----
            #pragma unroll
            for (int kt = 0; kt < 4; ++kt) {
                #pragma unroll
                for (int g = 0; g < 8; ++g) {
                    uint32_t vbh[4];
                    uint32_t vaddr = (kt*16 + (lane & 7) + ((lane >> 3) & 1) * 8) * AT_ROWB
                                   + g*32 + ((lane >> 4) & 1) * 16;
                    ldsm4t(vbh, uV + vaddr);
                    mma16816(of[2*g],   pa[kt], vbh[0], vbh[1]);
                    mma16816(of[2*g+1], pa[kt], vbh[2], vbh[3]);
                }
            }
        }

        // ---- epilogue: normalize, store f16 ----
        float inv0 = 1.0f / l0, inv1 = 1.0f / l1;
        const int b = bh >> 4, h = bh & 15;
        const int row0 = q0 + w*16 + (lane >> 2);
        size_t base0 = ((size_t)(b*T_ + row0)) * E_ + h*D_;
        size_t base1 = base0 + 8 * E_;
        #pragma unroll
        for (int n = 0; n < 16; ++n) {
            int col = n*8 + (lane & 3) * 2;
            *(uint32_t*)&g_Yh[base0 + col] = pack2(of[n][0] * inv0, of[n][1] * inv0);
            *(uint32_t*)&g_Yh[base1 + col] = pack2(of[n][2] * inv1, of[n][3] * inv1);
        }
        __syncthreads();   // all smem reads done before next tile's cp.async writes
    }
}

// ---------------------------------------------------------------------------
extern "C" void kernel_launch(void* const* d_in, const int* in_sizes, int n_in,
                              void* d_out, int out_size) {
    const float* x  = (const float*)d_in[0];
    const float* Wq = (const float*)d_in[1];
    const float* bq = (const float*)d_in[2];
    const float* Wk = (const float*)d_in[3];
    const float* bk = (const float*)d_in[4];
    const float* Wv = (const float*)d_in[5];
    const float* bv = (const float*)d_in[6];
    const float* Wo = (const float*)d_in[7];
    const float* bo = (const float*)d_in[8];
    float* out = (float*)d_out;

    cudaFuncSetAttribute(qkv_gemm, cudaFuncAttributeMaxDynamicSharedMemorySize, GEMM_SMEM);
    cudaFuncSetAttribute(out_gemm, cudaFuncAttributeMaxDynamicSharedMemorySize, GEMM_SMEM);
    cudaFuncSetAttribute(attn_tc,  cudaFuncAttributeMaxDynamicSharedMemorySize, ATTN_SMEM);

    theta_init_kernel<<<1, 64>>>();

    __half* Xh;
    cudaGetSymbolAddress((void**)&Xh, g_Xh);

    f2h_kernel<<<(M_*E_/4 + 255)/256, 256>>>(x, Xh, M_*E_/4);
    dim3 gw((WN_/4 + 255)/256, 4);
    w_f2h_kernel<<<gw, 256>>>(Wq, Wk, Wv, Wo);

    dim3 gq(E_/128, M_/128, 3);
    qkv_gemm<<<gq, 128, GEMM_SMEM>>>(bq, bk, bv);

    const int rope_total = B_*H_*T_*(D_/2);
    dim3 g2((rope_total + 255)/256, 2);
    rope_kernel<<<g2, 256>>>();

    dim3 g3(T_/128, B_*H_);
    attn_tc<<<g3, 128, ATTN_SMEM>>>();

    dim3 go(E_/128, M_/128);
    out_gemm<<<go, 128, GEMM_SMEM>>>(bo, out);
}